// round 5
// baseline (speedup 1.0000x reference)
#include <cuda_runtime.h>
#include <math.h>
#include <stdint.h>

#define D_MODEL 1024
#define D_INNER 2048
#define D_STATE 16
#define DT_RANK 64
#define NB 2
#define LSEQ 2048
#define BL (NB*LSEQ)            /* 4096 rows total */
#define XDBL_W 96               /* dt_rank + 2*d_state */
#define SPLITK 8

// ---------------- scratch (device globals; no allocation allowed) ----------------
__device__ float g_xz[(size_t)BL * 2 * D_INNER];
__device__ float g_u[(size_t)BL * D_INNER];
__device__ float g_xdbl[(size_t)BL * XDBL_W];
__device__ float g_delta[(size_t)BL * D_INNER];
__device__ float g_y[(size_t)BL * D_INNER];
__device__ float g_h[(size_t)BL * D_MODEL];
__device__ float g_part[(size_t)SPLITK * BL * XDBL_W];
// rounded-to-tf32 copies of MMA operands
__device__ float g_xr[(size_t)BL * D_MODEL];
__device__ float g_w1r[(size_t)2 * D_INNER * D_MODEL];
__device__ float g_w3r[(size_t)XDBL_W * D_INNER];
__device__ float g_w4r[(size_t)D_INNER * DT_RANK];
__device__ float g_w6r[(size_t)D_MODEL * D_INNER];

__device__ __forceinline__ float rna_tf32(float f) {
    uint32_t r; asm("cvt.rna.tf32.f32 %0, %1;" : "=r"(r) : "f"(f));
    return __uint_as_float(r);
}
__device__ __forceinline__ void mma_tf32(float* d, const uint32_t* a, const uint32_t* b) {
    asm volatile(
        "mma.sync.aligned.m16n8k8.row.col.f32.tf32.tf32.f32 "
        "{%0,%1,%2,%3}, {%4,%5,%6,%7}, {%8,%9}, {%0,%1,%2,%3};"
        : "+f"(d[0]), "+f"(d[1]), "+f"(d[2]), "+f"(d[3])
        : "r"(a[0]), "r"(a[1]), "r"(a[2]), "r"(a[3]), "r"(b[0]), "r"(b[1]));
}
__device__ __forceinline__ void cp16(uint32_t dst, const void* src, bool pred) {
    int sz = pred ? 16 : 0;
    asm volatile("cp.async.cg.shared.global [%0], [%1], 16, %2;"
                 :: "r"(dst), "l"(src), "r"(sz) : "memory");
}
#define CP_COMMIT() asm volatile("cp.async.commit_group;" ::: "memory")
#define CP_WAIT(n)  asm volatile("cp.async.wait_group %0;" :: "n"(n) : "memory")

// ================= tf32 mma.sync GEMM, cp.async 4-stage =================
// C[M,N] = A[M,K] * B[N,K]^T.  BM=256, BN=128, BK=32.
// 8 warps (4m x 2n), warp tile 64x64 (mt=4 x nt=8 of m16n8k8).
// EPI: 0 plain, 1 softplus(acc+aux[col]), 2 acc+aux[row*ldc+col]
#define SPITCH 36
#define A_FLOATS (256 * SPITCH)
#define B_FLOATS (128 * SPITCH)
#define STAGEF (A_FLOATS + B_FLOATS)
#define STAGEB (STAGEF * 4)
#define NSTAGE 4

template<int EPI>
__global__ __launch_bounds__(256, 1)
void gemm_cp(const float* __restrict__ A, int lda,
             const float* __restrict__ Bw, int ldb, int Nact,
             float* __restrict__ C, int ldc,
             const float* __restrict__ aux, int K, size_t csplit)
{
    extern __shared__ float smem[];
    const int tid = threadIdx.x;
    const int wid = tid >> 5;
    const int lane = tid & 31;
    const int g = lane >> 2;
    const int t4 = lane & 3;
    const int warp_m = wid >> 1;       // 0..3 -> *64 rows
    const int warp_n = wid & 1;        // 0..1 -> *64 cols
    const int bm = blockIdx.y * 256;
    const int bn = blockIdx.x * 128;

    const int kbase = blockIdx.z * K;
    C += (size_t)blockIdx.z * csplit;

    // A: 1 thread per row (32 floats); B: 2 threads per row (16 floats each)
    const int arow = tid;                   // 0..255
    const int brow = tid >> 1;              // 0..127
    const int bcol = (tid & 1) << 4;        // 0 or 16

    const bool bok = (bn + brow) < Nact;
    const float* Ap = A + (size_t)(bm + arow) * lda + kbase;
    const float* Bp = Bw + (size_t)(bn + brow) * ldb + kbase + bcol;

    uint32_t sbase;
    asm("{ .reg .u64 t; cvta.to.shared.u64 t, %1; cvt.u32.u64 %0, t; }"
        : "=r"(sbase) : "l"(smem));
    const uint32_t dA = sbase + (uint32_t)arow * SPITCH * 4;
    const uint32_t dB = sbase + A_FLOATS * 4 + ((uint32_t)brow * SPITCH + bcol) * 4;

    float acc[4][8][4];
#pragma unroll
    for (int mt = 0; mt < 4; mt++)
#pragma unroll
        for (int nt = 0; nt < 8; nt++)
#pragma unroll
            for (int q = 0; q < 4; q++) acc[mt][nt][q] = 0.f;

    const int NC = K >> 5;

    auto issue = [&](int c) {
        const uint32_t so = (uint32_t)(c & (NSTAGE - 1)) * STAGEB;
        const int k0 = c << 5;
#pragma unroll
        for (int i = 0; i < 8; i++)
            cp16(dA + so + i * 16, Ap + k0 + i * 4, true);
#pragma unroll
        for (int i = 0; i < 4; i++)
            cp16(dB + so + i * 16, Bp + k0 + i * 4, bok);
        CP_COMMIT();
    };
    auto compute = [&](int buf) {
        const float* As = smem + (size_t)buf * STAGEF;
        const float* Bs = As + A_FLOATS;
        const float* Ab = As + (warp_m * 64 + g) * SPITCH + t4;
        const float* Bb = Bs + (warp_n * 64 + g) * SPITCH + t4;
#pragma unroll
        for (int ks = 0; ks < 4; ks++) {
            const int k0 = ks << 3;
            uint32_t afr[4][4], bfr[8][2];
#pragma unroll
            for (int mt = 0; mt < 4; mt++) {
                const float* p = Ab + mt * 16 * SPITCH + k0;
                afr[mt][0] = __float_as_uint(p[0]);
                afr[mt][1] = __float_as_uint(p[8 * SPITCH]);
                afr[mt][2] = __float_as_uint(p[4]);
                afr[mt][3] = __float_as_uint(p[8 * SPITCH + 4]);
            }
#pragma unroll
            for (int nt = 0; nt < 8; nt++) {
                const float* p = Bb + nt * 8 * SPITCH + k0;
                bfr[nt][0] = __float_as_uint(p[0]);
                bfr[nt][1] = __float_as_uint(p[4]);
            }
#pragma unroll
            for (int mt = 0; mt < 4; mt++)
#pragma unroll
                for (int nt = 0; nt < 8; nt++)
                    mma_tf32(acc[mt][nt], afr[mt], bfr[nt]);
        }
    };

    const int npre = (NC < 3) ? NC : 3;
    for (int c = 0; c < npre; c++) issue(c);

    for (int c = 0; c < NC; c++) {
        const int rem = NC - 1 - c;
        if (rem >= 2)      CP_WAIT(2);
        else if (rem == 1) CP_WAIT(1);
        else               CP_WAIT(0);
        __syncthreads();
        if (c + 3 < NC) issue(c + 3);
        compute(c & (NSTAGE - 1));
    }

    // ---------------- epilogue ----------------
#pragma unroll
    for (int mt = 0; mt < 4; mt++) {
        const int r0 = bm + warp_m * 64 + mt * 16 + g;
#pragma unroll
        for (int nt = 0; nt < 8; nt++) {
            const int col = bn + warp_n * 64 + nt * 8 + 2 * t4;
            if (col >= Nact) continue;
#pragma unroll
            for (int hrow = 0; hrow < 2; hrow++) {
                const int r = r0 + hrow * 8;
                float2 v = make_float2(acc[mt][nt][hrow * 2], acc[mt][nt][hrow * 2 + 1]);
                if (EPI == 1) {
                    float2 bs = *(const float2*)(aux + col);
                    v.x += bs.x; v.y += bs.y;
                    v.x = fmaxf(v.x, 0.f) + log1pf(expf(-fabsf(v.x)));
                    v.y = fmaxf(v.y, 0.f) + log1pf(expf(-fabsf(v.y)));
                } else if (EPI == 2) {
                    float2 rv = *(const float2*)(aux + (size_t)r * ldc + col);
                    v.x += rv.x; v.y += rv.y;
                }
                *(float2*)(C + (size_t)r * ldc + col) = v;
            }
        }
    }
}

// ---------------- round fp32 -> tf32(RNA) copy ----------------
__global__ __launch_bounds__(256)
void round_kernel(const float* __restrict__ src, float* __restrict__ dst, int n)
{
    int i = blockIdx.x * blockDim.x + threadIdx.x;
    if (i < n) dst[i] = rna_tf32(src[i]);
}

// ---------------- split-K reduce (rounded output: feeds GEMM4 A) ----------------
__global__ __launch_bounds__(256)
void reduce_split_kernel()
{
    int idx = blockIdx.x * blockDim.x + threadIdx.x;
    if (idx >= BL * XDBL_W) return;
    float s = 0.f;
#pragma unroll
    for (int k = 0; k < SPLITK; k++)
        s += g_part[(size_t)k * BL * XDBL_W + idx];
    g_xdbl[idx] = rna_tf32(s);
}

// ---------------- causal depthwise conv + bias + SiLU (rounded: feeds GEMM3 A) ----------------
__global__ __launch_bounds__(256)
void conv_silu_kernel(const float* __restrict__ cw, const float* __restrict__ cb)
{
    int idx = blockIdx.x * blockDim.x + threadIdx.x;
    if (idx >= BL * D_INNER) return;
    int d = idx & (D_INNER - 1);
    int row = idx >> 11;
    int l = row & (LSEQ - 1);

    float w0 = cw[d * 4 + 0], w1 = cw[d * 4 + 1], w2 = cw[d * 4 + 2], w3 = cw[d * 4 + 3];
    float acc = cb[d];
    if (l >= 3) acc = fmaf(g_xz[(size_t)(row - 3) * (2 * D_INNER) + d], w0, acc);
    if (l >= 2) acc = fmaf(g_xz[(size_t)(row - 2) * (2 * D_INNER) + d], w1, acc);
    if (l >= 1) acc = fmaf(g_xz[(size_t)(row - 1) * (2 * D_INNER) + d], w2, acc);
    acc = fmaf(g_xz[(size_t)row * (2 * D_INNER) + d], w3, acc);
    float s = acc / (1.f + __expf(-acc));
    g_u[(size_t)row * D_INNER + d] = rna_tf32(s);
}

// ---------------- selective scan (rounded y: feeds GEMM6 A) ----------------
__global__ __launch_bounds__(256)
void scan_kernel(const float* __restrict__ A_log, const float* __restrict__ Dp)
{
    const int tid = threadIdx.x;
    const int ch = blockIdx.x * 32 + (tid >> 3);
    const int b = ch >> 11;
    const int d = ch & (D_INNER - 1);
    const int ls = tid & 7;
    const int n0 = ls << 1;

    const float A0 = -expf(A_log[d * D_STATE + n0]);
    const float A1 = -expf(A_log[d * D_STATE + n0 + 1]);
    const float Dd = Dp[d];

    float h0 = 0.f, h1 = 0.f;
    const float* xd = g_xdbl + (size_t)b * LSEQ * XDBL_W + DT_RANK + n0;
    const size_t base2 = (size_t)b * LSEQ * D_INNER + d;
    const size_t basez = (size_t)b * LSEQ * (2 * D_INNER) + D_INNER + d;

    float cD[4], cU[4], cZ[4];
    float2 cB[4], cC[4];

    auto load_group = [&](int l, float* D_, float* U_, float* Z_, float2* B_, float2* C_) {
#pragma unroll
        for (int j = 0; j < 4; j++) {
            size_t o2 = base2 + (size_t)(l + j) * D_INNER;
            D_[j] = g_delta[o2];
            U_[j] = g_u[o2];
        }
        if (ls == 0) {
#pragma unroll
            for (int j = 0; j < 4; j++)
                Z_[j] = g_xz[basez + (size_t)(l + j) * (2 * D_INNER)];
        }
#pragma unroll
        for (int j = 0; j < 4; j++) {
            const float* xr = xd + (size_t)(l + j) * XDBL_W;
            B_[j] = *(const float2*)(xr);
            C_[j] = *(const float2*)(xr + D_STATE);
        }
    };

    load_group(0, cD, cU, cZ, cB, cC);

    for (int l0 = 0; l0 < LSEQ; l0 += 4) {
        float nD[4], nU[4], nZ[4];
        float2 nB[4], nC[4];
        const bool more = (l0 + 4) < LSEQ;
        if (more) load_group(l0 + 4, nD, nU, nZ, nB, nC);

#pragma unroll
        for (int j = 0; j < 4; j++) {
            float du = cD[j] * cU[j];
            float e0 = __expf(cD[j] * A0);
            float e1 = __expf(cD[j] * A1);
            h0 = fmaf(e0, h0, du * cB[j].x);
            h1 = fmaf(e1, h1, du * cB[j].y);
            float y = fmaf(h0, cC[j].x, h1 * cC[j].y);
            y += __shfl_xor_sync(0xffffffffu, y, 1);
            y += __shfl_xor_sync(0xffffffffu, y, 2);
            y += __shfl_xor_sync(0xffffffffu, y, 4);
            if (ls == 0) {
                float z = cZ[j];
                float sz = z / (1.f + __expf(-z));
                g_y[base2 + (size_t)(l0 + j) * D_INNER] = rna_tf32((y + cU[j] * Dd) * sz);
            }
        }
        if (more) {
#pragma unroll
            for (int j = 0; j < 4; j++) {
                cD[j] = nD[j]; cU[j] = nU[j]; cZ[j] = nZ[j];
                cB[j] = nB[j]; cC[j] = nC[j];
            }
        }
    }
}

// ---------------- LayerNorm over last dim (1024) ----------------
__global__ __launch_bounds__(256)
void ln_kernel(const float* __restrict__ lnw, const float* __restrict__ lnb,
               float* __restrict__ out)
{
    int row = blockIdx.x;
    const float* hp = g_h + (size_t)row * D_MODEL;
    int tid = threadIdx.x;

    float v[4];
    float s = 0.f, sq = 0.f;
#pragma unroll
    for (int i = 0; i < 4; i++) {
        v[i] = hp[tid + i * 256];
        s += v[i];
        sq += v[i] * v[i];
    }
#pragma unroll
    for (int off = 16; off; off >>= 1) {
        s += __shfl_xor_sync(0xffffffffu, s, off);
        sq += __shfl_xor_sync(0xffffffffu, sq, off);
    }
    __shared__ float ss[8], ssq[8];
    __shared__ float mu_s, rs_s;
    if ((tid & 31) == 0) { ss[tid >> 5] = s; ssq[tid >> 5] = sq; }
    __syncthreads();
    if (tid == 0) {
        float S = 0.f, SQ = 0.f;
#pragma unroll
        for (int i = 0; i < 8; i++) { S += ss[i]; SQ += ssq[i]; }
        float mu = S * (1.f / D_MODEL);
        float var = SQ * (1.f / D_MODEL) - mu * mu;
        mu_s = mu;
        rs_s = rsqrtf(var + 1e-5f);
    }
    __syncthreads();
    float mu = mu_s, rs = rs_s;
#pragma unroll
    for (int i = 0; i < 4; i++) {
        int c = tid + i * 256;
        out[(size_t)row * D_MODEL + c] = (v[i] - mu) * rs * lnw[c] + lnb[c];
    }
}

// ---------------- host launch ----------------
extern "C" void kernel_launch(void* const* d_in, const int* in_sizes, int n_in,
                              void* d_out, int out_size)
{
    const float* x          = (const float*)d_in[0];
    const float* in_proj_w  = (const float*)d_in[1];
    const float* conv_w     = (const float*)d_in[2];
    const float* conv_b     = (const float*)d_in[3];
    const float* x_proj_w   = (const float*)d_in[4];
    const float* dt_proj_w  = (const float*)d_in[5];
    const float* dt_proj_b  = (const float*)d_in[6];
    const float* A_log      = (const float*)d_in[7];
    const float* Dp         = (const float*)d_in[8];
    const float* out_proj_w = (const float*)d_in[9];
    const float* ln_w       = (const float*)d_in[10];
    const float* ln_b       = (const float*)d_in[11];
    float* out = (float*)d_out;

    float *p_xz, *p_u, *p_xdbl, *p_delta, *p_y, *p_h, *p_part;
    float *p_xr, *p_w1r, *p_w3r, *p_w4r, *p_w6r;
    cudaGetSymbolAddress((void**)&p_xz,    g_xz);
    cudaGetSymbolAddress((void**)&p_u,     g_u);
    cudaGetSymbolAddress((void**)&p_xdbl,  g_xdbl);
    cudaGetSymbolAddress((void**)&p_delta, g_delta);
    cudaGetSymbolAddress((void**)&p_y,     g_y);
    cudaGetSymbolAddress((void**)&p_h,     g_h);
    cudaGetSymbolAddress((void**)&p_part,  g_part);
    cudaGetSymbolAddress((void**)&p_xr,    g_xr);
    cudaGetSymbolAddress((void**)&p_w1r,   g_w1r);
    cudaGetSymbolAddress((void**)&p_w3r,   g_w3r);
    cudaGetSymbolAddress((void**)&p_w4r,   g_w4r);
    cudaGetSymbolAddress((void**)&p_w6r,   g_w6r);

    const int smemB = NSTAGE * STAGEB;   // 4 * 55296 = 221184
    cudaFuncSetAttribute(gemm_cp<0>, cudaFuncAttributeMaxDynamicSharedMemorySize, smemB);
    cudaFuncSetAttribute(gemm_cp<1>, cudaFuncAttributeMaxDynamicSharedMemorySize, smemB);
    cudaFuncSetAttribute(gemm_cp<2>, cudaFuncAttributeMaxDynamicSharedMemorySize, smemB);

    // 0) round MMA operands (inputs + weights) to tf32-RNA
    auto roundN = [&](const float* s, float* dvc, int n) {
        round_kernel<<<(n + 255) / 256, 256>>>(s, dvc, n);
    };
    roundN(x,          p_xr,  BL * D_MODEL);
    roundN(in_proj_w,  p_w1r, 2 * D_INNER * D_MODEL);
    roundN(x_proj_w,   p_w3r, XDBL_W * D_INNER);
    roundN(dt_proj_w,  p_w4r, D_INNER * DT_RANK);
    roundN(out_proj_w, p_w6r, D_MODEL * D_INNER);

    // 1) xz = x @ in_proj_w^T            [4096,4096] K=1024
    gemm_cp<0><<<dim3(32, 16), 256, smemB>>>(p_xr, D_MODEL, p_w1r, D_MODEL, 2 * D_INNER,
                                             p_xz, 2 * D_INNER, nullptr, D_MODEL, 0);
    // 2) u = silu(causal_conv(xi) + cb)  (tf32-rounded)
    conv_silu_kernel<<<(BL * D_INNER + 255) / 256, 256>>>(conv_w, conv_b);
    // 3) x_dbl = u @ x_proj_w^T  [4096,96], split-K x8 + reduce
    gemm_cp<0><<<dim3(1, 16, SPLITK), 256, smemB>>>(p_u, D_INNER, p_w3r, D_INNER, XDBL_W,
                                                    p_part, XDBL_W, nullptr,
                                                    D_INNER / SPLITK, (size_t)BL * XDBL_W);
    reduce_split_kernel<<<(BL * XDBL_W + 255) / 256, 256>>>();
    // 4) delta = softplus(dt @ dt_proj_w^T + b)   [4096,2048] K=64
    gemm_cp<1><<<dim3(16, 16), 256, smemB>>>(p_xdbl, XDBL_W, p_w4r, DT_RANK, D_INNER,
                                             p_delta, D_INNER, dt_proj_b, DT_RANK, 0);
    // 5) selective scan + skip + gate    (tf32-rounded y)
    scan_kernel<<<128, 256>>>(A_log, Dp);
    // 6) h = y @ out_proj_w^T + x        [4096,1024] K=2048
    gemm_cp<2><<<dim3(8, 16), 256, smemB>>>(p_y, D_INNER, p_w6r, D_INNER, D_MODEL,
                                            p_h, D_MODEL, x, D_INNER, 0);
    // 7) LayerNorm -> out
    ln_kernel<<<BL, 256>>>(ln_w, ln_b, out);
}

// round 6
// speedup vs baseline: 1.1789x; 1.1789x over previous
#include <cuda_runtime.h>
#include <cuda_fp16.h>
#include <math.h>
#include <stdint.h>

#define D_MODEL 1024
#define D_INNER 2048
#define D_STATE 16
#define DT_RANK 64
#define NB 2
#define LSEQ 2048
#define BL (NB*LSEQ)            /* 4096 rows total */
#define XDBL_W 96
#define SPLITK 8

// ---------------- scratch (device globals) ----------------
__device__ float  g_xz[(size_t)BL * 2 * D_INNER];       // fp32: conv input + z gate
__device__ float  g_delta[(size_t)BL * D_INNER];        // fp32: scan input
__device__ float  g_h[(size_t)BL * D_MODEL];            // fp32: pre-LN
__device__ float  g_part[(size_t)SPLITK * BL * XDBL_W]; // split-K partials
// fp16 GEMM operands
__device__ __half g_uh[(size_t)BL * D_INNER];
__device__ __half g_xdbl_h[(size_t)BL * XDBL_W];
__device__ __half g_yh[(size_t)BL * D_INNER];
__device__ __half g_xh[(size_t)BL * D_MODEL];
__device__ __half g_w1h[(size_t)2 * D_INNER * D_MODEL];
__device__ __half g_w3h[(size_t)XDBL_W * D_INNER];
__device__ __half g_w4h[(size_t)D_INNER * DT_RANK];
__device__ __half g_w6h[(size_t)D_MODEL * D_INNER];

__device__ __forceinline__ void mma_f16(float* d, const uint32_t* a, const uint32_t* b) {
    asm volatile(
        "mma.sync.aligned.m16n8k16.row.col.f32.f16.f16.f32 "
        "{%0,%1,%2,%3}, {%4,%5,%6,%7}, {%8,%9}, {%0,%1,%2,%3};"
        : "+f"(d[0]), "+f"(d[1]), "+f"(d[2]), "+f"(d[3])
        : "r"(a[0]), "r"(a[1]), "r"(a[2]), "r"(a[3]), "r"(b[0]), "r"(b[1]));
}
__device__ __forceinline__ void ldsm4(uint32_t* r, uint32_t addr) {
    asm volatile("ldmatrix.sync.aligned.m8n8.x4.shared.b16 {%0,%1,%2,%3}, [%4];"
                 : "=r"(r[0]), "=r"(r[1]), "=r"(r[2]), "=r"(r[3]) : "r"(addr));
}
__device__ __forceinline__ void cp16(uint32_t dst, const void* src, bool pred) {
    int sz = pred ? 16 : 0;
    asm volatile("cp.async.cg.shared.global [%0], [%1], 16, %2;"
                 :: "r"(dst), "l"(src), "r"(sz) : "memory");
}
#define CP_COMMIT() asm volatile("cp.async.commit_group;" ::: "memory")
#define CP_WAIT(n)  asm volatile("cp.async.wait_group %0;" :: "n"(n) : "memory")

// ================= fp16 mma.sync GEMM, cp.async 4-stage, ldmatrix =================
// C[M,N](fp32) = A[M,K]h * B[N,K]h^T.  BM=128, BN=128, BK=32.
// 8 warps (4m x 2n), warp tile 32x64: mt=2 x nt=8 of m16n8k16.
#define SPITCH_H 40                       /* halves per smem row (80B, LDSM conflict-free) */
#define A_HALVES (128 * SPITCH_H)
#define STAGE_HALVES (2 * A_HALVES)
#define STAGEB (STAGE_HALVES * 2)         /* bytes: 20480 */
#define NSTAGE 4

template<int EPI>
__global__ __launch_bounds__(256, 2)
void gemm_h(const __half* __restrict__ A, int lda,
            const __half* __restrict__ Bw, int ldb, int Nact,
            float* __restrict__ C, int ldc,
            const float* __restrict__ aux, int K, size_t csplit)
{
    extern __shared__ __half smem[];
    const int tid = threadIdx.x;
    const int wid = tid >> 5;
    const int lane = tid & 31;
    const int g = lane >> 2;
    const int t4 = lane & 3;
    const int warp_m = wid >> 1;
    const int warp_n = wid & 1;
    const int bm = blockIdx.y * 128;
    const int bn = blockIdx.x * 128;

    const int kbase = blockIdx.z * K;
    C += (size_t)blockIdx.z * csplit;

    const int row = tid >> 1;              // 0..127 (shared by A and B loads)
    const int seg = (tid & 1) << 4;        // 0 or 16 halves

    const bool bok = (bn + row) < Nact;
    const __half* Ap = A + (size_t)(bm + row) * lda + kbase + seg;
    const __half* Bp = Bw + (size_t)(bn + row) * ldb + kbase + seg;

    uint32_t sbase;
    asm("{ .reg .u64 t; cvta.to.shared.u64 t, %1; cvt.u32.u64 %0, t; }"
        : "=r"(sbase) : "l"(smem));
    const uint32_t dA = sbase + ((uint32_t)row * SPITCH_H + seg) * 2;
    const uint32_t dB = dA + A_HALVES * 2;

    // ldmatrix lane addresses (byte offsets within a stage)
    // A (mt): rows m = warp_m*32 + mt*16 + (lane&15); k-col offset (lane>>4)*8
    uint32_t aoff[2], boff[4];
#pragma unroll
    for (int mt = 0; mt < 2; mt++)
        aoff[mt] = (((uint32_t)(warp_m * 32 + mt * 16 + (lane & 15))) * SPITCH_H
                    + ((lane >> 4) << 3)) * 2;
    // B (nt2): rows n = warp_n*64 + nt2*16 + (lane&7) + ((lane>>4)<<3); k-col ((lane>>3)&1)*8
#pragma unroll
    for (int nt2 = 0; nt2 < 4; nt2++)
        boff[nt2] = A_HALVES * 2 +
                    (((uint32_t)(warp_n * 64 + nt2 * 16 + (lane & 7) + ((lane >> 4) << 3)))
                     * SPITCH_H + (((lane >> 3) & 1) << 3)) * 2;

    float acc[2][8][4];
#pragma unroll
    for (int mt = 0; mt < 2; mt++)
#pragma unroll
        for (int nt = 0; nt < 8; nt++)
#pragma unroll
            for (int q = 0; q < 4; q++) acc[mt][nt][q] = 0.f;

    const int NC = K >> 5;

    auto issue = [&](int c) {
        const uint32_t so = (uint32_t)(c & (NSTAGE - 1)) * STAGEB;
        const int k0 = c << 5;
        cp16(dA + so,      Ap + k0,     true);
        cp16(dA + so + 16, Ap + k0 + 8, true);
        cp16(dB + so,      Bp + k0,     bok);
        cp16(dB + so + 16, Bp + k0 + 8, bok);
        CP_COMMIT();
    };
    auto compute = [&](int buf) {
        const uint32_t so = sbase + (uint32_t)buf * STAGEB;
#pragma unroll
        for (int ks = 0; ks < 2; ks++) {
            const uint32_t kb = so + ks * 32;   // +16 halves per k16 step
            uint32_t afr[2][4], bfr[4][4];
#pragma unroll
            for (int mt = 0; mt < 2; mt++) ldsm4(afr[mt], kb + aoff[mt]);
#pragma unroll
            for (int nt2 = 0; nt2 < 4; nt2++) ldsm4(bfr[nt2], kb + boff[nt2]);
#pragma unroll
            for (int mt = 0; mt < 2; mt++)
#pragma unroll
                for (int nt2 = 0; nt2 < 4; nt2++) {
                    mma_f16(acc[mt][nt2 * 2],     afr[mt], &bfr[nt2][0]);
                    mma_f16(acc[mt][nt2 * 2 + 1], afr[mt], &bfr[nt2][2]);
                }
        }
    };

    const int npre = (NC < 3) ? NC : 3;
    for (int c = 0; c < npre; c++) issue(c);

    for (int c = 0; c < NC; c++) {
        const int rem = NC - 1 - c;
        if (rem >= 2)      CP_WAIT(2);
        else if (rem == 1) CP_WAIT(1);
        else               CP_WAIT(0);
        __syncthreads();
        if (c + 3 < NC) issue(c + 3);
        compute(c & (NSTAGE - 1));
        __syncthreads();
    }

    // ---------------- epilogue ----------------
#pragma unroll
    for (int mt = 0; mt < 2; mt++) {
        const int r0 = bm + warp_m * 32 + mt * 16 + g;
#pragma unroll
        for (int nt = 0; nt < 8; nt++) {
            const int col = bn + warp_n * 64 + nt * 8 + 2 * t4;
            if (col >= Nact) continue;
#pragma unroll
            for (int hrow = 0; hrow < 2; hrow++) {
                const int r = r0 + hrow * 8;
                float2 v = make_float2(acc[mt][nt][hrow * 2], acc[mt][nt][hrow * 2 + 1]);
                if (EPI == 1) {
                    float2 bs = *(const float2*)(aux + col);
                    v.x += bs.x; v.y += bs.y;
                    v.x = fmaxf(v.x, 0.f) + log1pf(expf(-fabsf(v.x)));
                    v.y = fmaxf(v.y, 0.f) + log1pf(expf(-fabsf(v.y)));
                } else if (EPI == 2) {
                    float2 rv = *(const float2*)(aux + (size_t)r * ldc + col);
                    v.x += rv.x; v.y += rv.y;
                }
                *(float2*)(C + (size_t)r * ldc + col) = v;
            }
        }
    }
}

// ---------------- fp32 -> fp16 conversion (vectorized) ----------------
__global__ __launch_bounds__(256)
void tohalf_kernel(const float* __restrict__ src, __half* __restrict__ dst, int n4)
{
    int i = blockIdx.x * blockDim.x + threadIdx.x;
    if (i >= n4) return;
    float4 v = ((const float4*)src)[i];
    __half2 h0 = __floats2half2_rn(v.x, v.y);
    __half2 h1 = __floats2half2_rn(v.z, v.w);
    ((__half2*)dst)[i * 2]     = h0;
    ((__half2*)dst)[i * 2 + 1] = h1;
}

// ---------------- split-K reduce -> half xdbl ----------------
__global__ __launch_bounds__(256)
void reduce_split_kernel()
{
    int idx = blockIdx.x * blockDim.x + threadIdx.x;
    if (idx >= BL * XDBL_W) return;
    float s = 0.f;
#pragma unroll
    for (int k = 0; k < SPLITK; k++)
        s += g_part[(size_t)k * BL * XDBL_W + idx];
    g_xdbl_h[idx] = __float2half_rn(s);
}

// ---------------- causal depthwise conv + bias + SiLU -> half u ----------------
__global__ __launch_bounds__(256)
void conv_silu_kernel(const float* __restrict__ cw, const float* __restrict__ cb)
{
    int idx = blockIdx.x * blockDim.x + threadIdx.x;
    if (idx >= BL * D_INNER) return;
    int d = idx & (D_INNER - 1);
    int row = idx >> 11;
    int l = row & (LSEQ - 1);

    float w0 = cw[d * 4 + 0], w1 = cw[d * 4 + 1], w2 = cw[d * 4 + 2], w3 = cw[d * 4 + 3];
    float acc = cb[d];
    if (l >= 3) acc = fmaf(g_xz[(size_t)(row - 3) * (2 * D_INNER) + d], w0, acc);
    if (l >= 2) acc = fmaf(g_xz[(size_t)(row - 2) * (2 * D_INNER) + d], w1, acc);
    if (l >= 1) acc = fmaf(g_xz[(size_t)(row - 1) * (2 * D_INNER) + d], w2, acc);
    acc = fmaf(g_xz[(size_t)row * (2 * D_INNER) + d], w3, acc);
    float s = acc / (1.f + __expf(-acc));
    g_uh[(size_t)row * D_INNER + d] = __float2half_rn(s);
}

// ---------------- selective scan: 8 lanes/channel, 2 states/lane, time-unroll 4 ----------------
__global__ __launch_bounds__(256)
void scan_kernel(const float* __restrict__ A_log, const float* __restrict__ Dp)
{
    const int tid = threadIdx.x;
    const int ch = blockIdx.x * 32 + (tid >> 3);
    const int b = ch >> 11;
    const int d = ch & (D_INNER - 1);
    const int ls = tid & 7;
    const int n0 = ls << 1;

    const float A0 = -expf(A_log[d * D_STATE + n0]);
    const float A1 = -expf(A_log[d * D_STATE + n0 + 1]);
    const float Dd = Dp[d];

    float h0 = 0.f, h1 = 0.f;
    const __half* xd = g_xdbl_h + (size_t)b * LSEQ * XDBL_W + DT_RANK + n0;
    const size_t base2 = (size_t)b * LSEQ * D_INNER + d;
    const size_t basez = (size_t)b * LSEQ * (2 * D_INNER) + D_INNER + d;

    float cD[4], cU[4], cZ[4];
    float2 cB[4], cC[4];

    auto load_group = [&](int l, float* D_, float* U_, float* Z_, float2* B_, float2* C_) {
#pragma unroll
        for (int j = 0; j < 4; j++) {
            size_t o2 = base2 + (size_t)(l + j) * D_INNER;
            D_[j] = g_delta[o2];
            U_[j] = __half2float(g_uh[o2]);
        }
        if (ls == 0) {
#pragma unroll
            for (int j = 0; j < 4; j++)
                Z_[j] = g_xz[basez + (size_t)(l + j) * (2 * D_INNER)];
        }
#pragma unroll
        for (int j = 0; j < 4; j++) {
            const __half* xr = xd + (size_t)(l + j) * XDBL_W;
            B_[j] = __half22float2(*(const __half2*)(xr));
            C_[j] = __half22float2(*(const __half2*)(xr + D_STATE));
        }
    };

    load_group(0, cD, cU, cZ, cB, cC);

    for (int l0 = 0; l0 < LSEQ; l0 += 4) {
        float nD[4], nU[4], nZ[4];
        float2 nB[4], nC[4];
        const bool more = (l0 + 4) < LSEQ;
        if (more) load_group(l0 + 4, nD, nU, nZ, nB, nC);

#pragma unroll
        for (int j = 0; j < 4; j++) {
            float du = cD[j] * cU[j];
            float e0 = __expf(cD[j] * A0);
            float e1 = __expf(cD[j] * A1);
            h0 = fmaf(e0, h0, du * cB[j].x);
            h1 = fmaf(e1, h1, du * cB[j].y);
            float y = fmaf(h0, cC[j].x, h1 * cC[j].y);
            y += __shfl_xor_sync(0xffffffffu, y, 1);
            y += __shfl_xor_sync(0xffffffffu, y, 2);
            y += __shfl_xor_sync(0xffffffffu, y, 4);
            if (ls == 0) {
                float z = cZ[j];
                float sz = z / (1.f + __expf(-z));
                g_yh[base2 + (size_t)(l0 + j) * D_INNER] =
                    __float2half_rn((y + cU[j] * Dd) * sz);
            }
        }
        if (more) {
#pragma unroll
            for (int j = 0; j < 4; j++) {
                cD[j] = nD[j]; cU[j] = nU[j]; cZ[j] = nZ[j];
                cB[j] = nB[j]; cC[j] = nC[j];
            }
        }
    }
}

// ---------------- LayerNorm over last dim (1024) ----------------
__global__ __launch_bounds__(256)
void ln_kernel(const float* __restrict__ lnw, const float* __restrict__ lnb,
               float* __restrict__ out)
{
    int row = blockIdx.x;
    const float* hp = g_h + (size_t)row * D_MODEL;
    int tid = threadIdx.x;

    float v[4];
    float s = 0.f, sq = 0.f;
#pragma unroll
    for (int i = 0; i < 4; i++) {
        v[i] = hp[tid + i * 256];
        s += v[i];
        sq += v[i] * v[i];
    }
#pragma unroll
    for (int off = 16; off; off >>= 1) {
        s += __shfl_xor_sync(0xffffffffu, s, off);
        sq += __shfl_xor_sync(0xffffffffu, sq, off);
    }
    __shared__ float ss[8], ssq[8];
    __shared__ float mu_s, rs_s;
    if ((tid & 31) == 0) { ss[tid >> 5] = s; ssq[tid >> 5] = sq; }
    __syncthreads();
    if (tid == 0) {
        float S = 0.f, SQ = 0.f;
#pragma unroll
        for (int i = 0; i < 8; i++) { S += ss[i]; SQ += ssq[i]; }
        float mu = S * (1.f / D_MODEL);
        float var = SQ * (1.f / D_MODEL) - mu * mu;
        mu_s = mu;
        rs_s = rsqrtf(var + 1e-5f);
    }
    __syncthreads();
    float mu = mu_s, rs = rs_s;
#pragma unroll
    for (int i = 0; i < 4; i++) {
        int c = tid + i * 256;
        out[(size_t)row * D_MODEL + c] = (v[i] - mu) * rs * lnw[c] + lnb[c];
    }
}

// ---------------- host launch ----------------
extern "C" void kernel_launch(void* const* d_in, const int* in_sizes, int n_in,
                              void* d_out, int out_size)
{
    const float* x          = (const float*)d_in[0];
    const float* in_proj_w  = (const float*)d_in[1];
    const float* conv_w     = (const float*)d_in[2];
    const float* conv_b     = (const float*)d_in[3];
    const float* x_proj_w   = (const float*)d_in[4];
    const float* dt_proj_w  = (const float*)d_in[5];
    const float* dt_proj_b  = (const float*)d_in[6];
    const float* A_log      = (const float*)d_in[7];
    const float* Dp         = (const float*)d_in[8];
    const float* out_proj_w = (const float*)d_in[9];
    const float* ln_w       = (const float*)d_in[10];
    const float* ln_b       = (const float*)d_in[11];
    float* out = (float*)d_out;

    float *p_xz, *p_delta, *p_h, *p_part;
    __half *p_uh, *p_xdblh, *p_yh, *p_xh, *p_w1h, *p_w3h, *p_w4h, *p_w6h;
    cudaGetSymbolAddress((void**)&p_xz,    g_xz);
    cudaGetSymbolAddress((void**)&p_delta, g_delta);
    cudaGetSymbolAddress((void**)&p_h,     g_h);
    cudaGetSymbolAddress((void**)&p_part,  g_part);
    cudaGetSymbolAddress((void**)&p_uh,    g_uh);
    cudaGetSymbolAddress((void**)&p_xdblh, g_xdbl_h);
    cudaGetSymbolAddress((void**)&p_yh,    g_yh);
    cudaGetSymbolAddress((void**)&p_xh,    g_xh);
    cudaGetSymbolAddress((void**)&p_w1h,   g_w1h);
    cudaGetSymbolAddress((void**)&p_w3h,   g_w3h);
    cudaGetSymbolAddress((void**)&p_w4h,   g_w4h);
    cudaGetSymbolAddress((void**)&p_w6h,   g_w6h);

    const int smemB = NSTAGE * STAGEB;   // 4 * 20480 = 81920
    cudaFuncSetAttribute(gemm_h<0>, cudaFuncAttributeMaxDynamicSharedMemorySize, smemB);
    cudaFuncSetAttribute(gemm_h<1>, cudaFuncAttributeMaxDynamicSharedMemorySize, smemB);
    cudaFuncSetAttribute(gemm_h<2>, cudaFuncAttributeMaxDynamicSharedMemorySize, smemB);

    auto cvt = [&](const float* s, __half* dvc, int n) {
        tohalf_kernel<<<(n / 4 + 255) / 256, 256>>>(s, dvc, n / 4);
    };
    cvt(x,          p_xh,  BL * D_MODEL);
    cvt(in_proj_w,  p_w1h, 2 * D_INNER * D_MODEL);
    cvt(x_proj_w,   p_w3h, XDBL_W * D_INNER);
    cvt(dt_proj_w,  p_w4h, D_INNER * DT_RANK);
    cvt(out_proj_w, p_w6h, D_MODEL * D_INNER);

    // 1) xz = x @ in_proj_w^T            [4096,4096] K=1024
    gemm_h<0><<<dim3(32, 32), 256, smemB>>>(p_xh, D_MODEL, p_w1h, D_MODEL, 2 * D_INNER,
                                            p_xz, 2 * D_INNER, nullptr, D_MODEL, 0);
    // 2) u = silu(causal_conv(xi) + cb)  -> half
    conv_silu_kernel<<<(BL * D_INNER + 255) / 256, 256>>>(conv_w, conv_b);
    // 3) x_dbl = u @ x_proj_w^T  [4096,96], split-K x8 + reduce -> half
    gemm_h<0><<<dim3(1, 32, SPLITK), 256, smemB>>>(p_uh, D_INNER, p_w3h, D_INNER, XDBL_W,
                                                   p_part, XDBL_W, nullptr,
                                                   D_INNER / SPLITK, (size_t)BL * XDBL_W);
    reduce_split_kernel<<<(BL * XDBL_W + 255) / 256, 256>>>();
    // 4) delta = softplus(dt @ dt_proj_w^T + b)   [4096,2048] K=64
    gemm_h<1><<<dim3(16, 32), 256, smemB>>>(p_xdblh, XDBL_W, p_w4h, DT_RANK, D_INNER,
                                            p_delta, D_INNER, dt_proj_b, DT_RANK, 0);
    // 5) selective scan + skip + gate -> half y
    scan_kernel<<<128, 256>>>(A_log, Dp);
    // 6) h = y @ out_proj_w^T + x        [4096,1024] K=2048
    gemm_h<2><<<dim3(8, 32), 256, smemB>>>(p_yh, D_INNER, p_w6h, D_INNER, D_MODEL,
                                           p_h, D_MODEL, x, D_INNER, 0);
    // 7) LayerNorm -> out
    ln_kernel<<<BL, 256>>>(ln_w, ln_b, out);
}